// round 15
// baseline (speedup 1.0000x reference)
#include <cuda_runtime.h>
#include <cuda_fp16.h>
#include <math.h>
#include <stdint.h>

#define TT      8192
#define DIN     1024
#define DOUT    1024
#define MTR     64
#define CCT     16
#define NCH     1024
#define CHUNK   32
#define NCHUNK  256           // TT/CHUNK
#define DMIX    2048
#define KTOT    (DMIX + DIN)  // 3072

// Scratch
__device__ float g_pre[TT * MTR];
__device__ float g_Bre[NCHUNK * NCH];
__device__ float g_Bim[NCHUNK * NCH];
__device__ float g_cRe[NCHUNK * NCH];
__device__ float g_cIm[NCHUNK * NCH];
__device__ int   g_any[NCHUNK];
// single fp16 planes for the big GEMM
__device__ __half g_zin16[TT * DMIX];
__device__ __half g_x16[TT * DIN];
__device__ __half g_wm16[DOUT * DMIX];
__device__ __half g_ws16[DOUT * DIN];

// ---------------------------------------------------------------------------
// helpers
// ---------------------------------------------------------------------------
__device__ __forceinline__ uint32_t smem_u32(const void* p) {
    uint32_t a;
    asm("{ .reg .u64 t; cvta.to.shared.u64 t, %1; cvt.u32.u64 %0, t; }" : "=r"(a) : "l"(p));
    return a;
}
__device__ __forceinline__ void ldsm4(uint32_t* r, uint32_t addr) {
    asm volatile("ldmatrix.sync.aligned.m8n8.x4.shared.b16 {%0,%1,%2,%3}, [%4];"
                 : "=r"(r[0]), "=r"(r[1]), "=r"(r[2]), "=r"(r[3]) : "r"(addr));
}
__device__ __forceinline__ void mma_f16(float* d, const uint32_t* a, const uint32_t* b) {
    asm volatile("mma.sync.aligned.m16n8k16.row.col.f32.f16.f16.f32 "
                 "{%0,%1,%2,%3}, {%4,%5,%6,%7}, {%8,%9}, {%0,%1,%2,%3};"
                 : "+f"(d[0]), "+f"(d[1]), "+f"(d[2]), "+f"(d[3])
                 : "r"(a[0]), "r"(a[1]), "r"(a[2]), "r"(a[3]), "r"(b[0]), "r"(b[1]));
}
__device__ __forceinline__ void cp16(uint32_t dst, const void* src) {
    asm volatile("cp.async.cg.shared.global [%0], [%1], 16;"
                 :: "r"(dst), "l"(src) : "memory");
}
#define CP_COMMIT() asm volatile("cp.async.commit_group;" ::: "memory")
#define CP_WAIT(n)  asm volatile("cp.async.wait_group %0;" :: "n"(n) : "memory")

__device__ __forceinline__ uint32_t pack2h(__half a, __half b) {
    return (uint32_t)__half_as_ushort(a) | ((uint32_t)__half_as_ushort(b) << 16);
}

// ---------------------------------------------------------------------------
// K0: x, Wmix, Wskip -> single fp16 planes
// ---------------------------------------------------------------------------
#define N4_X   (TT * DIN / 4)
#define N4_WM  (DOUT * DMIX / 4)
#define N4_WS  (DOUT * DIN / 4)
#define N4_ALL (N4_X + N4_WM + N4_WS)

__global__ __launch_bounds__(256) void k_split(const float* __restrict__ x,
                                               const float* __restrict__ Wmix,
                                               const float* __restrict__ Wskip) {
    int i = blockIdx.x * blockDim.x + threadIdx.x;
    if (i >= N4_ALL) return;
    const float* src; __half* dst; int j;
    if (i < N4_X)              { src = x;     dst = g_x16;  j = i; }
    else if (i < N4_X + N4_WM) { src = Wmix;  dst = g_wm16; j = i - N4_X; }
    else                       { src = Wskip; dst = g_ws16; j = i - N4_X - N4_WM; }
    float4 v = ((const float4*)src)[j];
    ((uint2*)dst)[j] = make_uint2(
        pack2h(__float2half_rn(v.x), __float2half_rn(v.y)),
        pack2h(__float2half_rn(v.z), __float2half_rn(v.w)));
}

// ---------------------------------------------------------------------------
// K1: pre = rownorm(x @ W_pre^T + b_pre)
// ---------------------------------------------------------------------------
__global__ __launch_bounds__(256) void k_pre(const float* __restrict__ x,
                                             const float* __restrict__ Wp,
                                             const float* __restrict__ bp) {
    __shared__ float xs[32][65];
    __shared__ float ws[32][65];
    __shared__ float nrm[64];
    const int tid = threadIdx.x;
    const int ty = tid >> 4, tx = tid & 15;
    const int row0 = blockIdx.x * 64;

    float acc[4][4];
#pragma unroll
    for (int i = 0; i < 4; i++)
#pragma unroll
        for (int j = 0; j < 4; j++) acc[i][j] = 0.f;

    for (int k0 = 0; k0 < DIN; k0 += 32) {
#pragma unroll
        for (int r = 0; r < 8; r++) {
            int idx = tid + r * 256;
            int m = idx >> 5, k = idx & 31;
            xs[k][m] = x[(size_t)(row0 + m) * DIN + k0 + k];
            ws[k][m] = Wp[(size_t)m * DIN + k0 + k];
        }
        __syncthreads();
#pragma unroll
        for (int kk = 0; kk < 32; kk++) {
            float av[4], bv[4];
#pragma unroll
            for (int i = 0; i < 4; i++) av[i] = xs[kk][ty * 4 + i];
#pragma unroll
            for (int j = 0; j < 4; j++) bv[j] = ws[kk][tx * 4 + j];
#pragma unroll
            for (int i = 0; i < 4; i++)
#pragma unroll
                for (int j = 0; j < 4; j++) acc[i][j] += av[i] * bv[j];
        }
        __syncthreads();
    }
#pragma unroll
    for (int j = 0; j < 4; j++) {
        float b = bp[tx * 4 + j];
#pragma unroll
        for (int i = 0; i < 4; i++) acc[i][j] += b;
    }
    if (tid < 64) nrm[tid] = 0.f;
    __syncthreads();
#pragma unroll
    for (int i = 0; i < 4; i++) {
        float s = 0.f;
#pragma unroll
        for (int j = 0; j < 4; j++) s += acc[i][j] * acc[i][j];
        atomicAdd(&nrm[ty * 4 + i], s);
    }
    __syncthreads();
#pragma unroll
    for (int i = 0; i < 4; i++) {
        float inv = 1.0f / (1e-6f + sqrtf(nrm[ty * 4 + i]));
#pragma unroll
        for (int j = 0; j < 4; j++)
            g_pre[(size_t)(row0 + ty * 4 + i) * MTR + tx * 4 + j] = acc[i][j] * inv;
    }
}

// ---------------------------------------------------------------------------
// K2a: per-chunk local scan from S=0 -> transfer (B, anyStart).  CHUNK=32.
// ---------------------------------------------------------------------------
__global__ __launch_bounds__(256) void k_chunk(const int* __restrict__ start,
                                               const float* __restrict__ a,
                                               const float* __restrict__ bfreq) {
    __shared__ float sp[CHUNK][MTR];
    __shared__ int ss[CHUNK];
    __shared__ int sAny;
    const int tid = threadIdx.x;
    const int ck = blockIdx.x;
    const int t0 = ck * CHUNK;

    for (int idx = tid; idx < CHUNK * MTR; idx += 256)
        sp[idx >> 6][idx & 63] = g_pre[(size_t)(t0 + (idx >> 6)) * MTR + (idx & 63)];
    if (tid < CHUNK) ss[tid] = (start[t0 + tid] != 0);
    if (tid == 0) sAny = 0;
    __syncthreads();
    if (tid < CHUNK && ss[tid]) atomicOr(&sAny, 1);

    const int m = tid >> 2;
    const float gmag = expf(-fabsf(a[m]));
    float gre[4], gim[4], Sre[4], Sim[4];
#pragma unroll
    for (int q = 0; q < 4; q++) {
        int c = ((tid & 3) << 2) + q;
        float sv, cv; sincosf(bfreq[c], &sv, &cv);
        gre[q] = gmag * cv; gim[q] = gmag * sv;
        Sre[q] = 0.f; Sim[q] = 0.f;
    }
    for (int t = 0; t < CHUNK; t++) {
        float p = sp[t][m];
        float keep = ss[t] ? 0.f : 1.f;
#pragma unroll
        for (int q = 0; q < 4; q++) {
            float r  = keep * (gre[q] * Sre[q] - gim[q] * Sim[q]) + p;
            float im = keep * (gre[q] * Sim[q] + gim[q] * Sre[q]);
            Sre[q] = r; Sim[q] = im;
        }
    }
#pragma unroll
    for (int q = 0; q < 4; q++) {
        int ch = tid * 4 + q;
        g_Bre[(size_t)ck * NCH + ch] = Sre[q];
        g_Bim[(size_t)ck * NCH + ch] = Sim[q];
    }
    __syncthreads();
    if (tid == 0) g_any[ck] = sAny;
}

// ---------------------------------------------------------------------------
// K2b: sequential chain, parallel over channels: 32 blocks x 32 channels.
// ---------------------------------------------------------------------------
#define CB 16
__global__ __launch_bounds__(32) void k_chain(const float* __restrict__ s_re0,
                                              const float* __restrict__ s_im0,
                                              const float* __restrict__ a,
                                              const float* __restrict__ bfreq,
                                              float* stateOut) {
    __shared__ float keep_s[NCHUNK];
    const int ch = blockIdx.x * 32 + threadIdx.x;
    const int m = ch >> 4, c = ch & 15;
    for (int idx = threadIdx.x; idx < NCHUNK; idx += 32)
        keep_s[idx] = g_any[idx] ? 0.f : 1.f;
    __syncthreads();

    const float Amag = expf(-(float)CHUNK * fabsf(a[m]));
    float sv, cv; sincosf((float)CHUNK * bfreq[c], &sv, &cv);
    const float Are = Amag * cv, Aim = Amag * sv;
    float Sre = s_re0[ch], Sim = s_im0[ch];

    for (int kb = 0; kb < NCHUNK; kb += CB) {
        float br[CB], bi[CB];
#pragma unroll
        for (int q = 0; q < CB; q++) {
            br[q] = g_Bre[(size_t)(kb + q) * NCH + ch];
            bi[q] = g_Bim[(size_t)(kb + q) * NCH + ch];
        }
#pragma unroll
        for (int q = 0; q < CB; q++) {
            g_cRe[(size_t)(kb + q) * NCH + ch] = Sre;
            g_cIm[(size_t)(kb + q) * NCH + ch] = Sim;
            float keep = keep_s[kb + q];
            float r  = keep * (Are * Sre - Aim * Sim) + br[q];
            float im = keep * (Are * Sim + Aim * Sre) + bi[q];
            Sre = r; Sim = im;
        }
    }
    stateOut[ch]       = Sre;   // planar: re then im
    stateOut[NCH + ch] = Sim;
}

// ---------------------------------------------------------------------------
// K2c: re-scan with true carry, emit zin as a single fp16 plane.  CHUNK=32.
// ---------------------------------------------------------------------------
__global__ __launch_bounds__(256) void k_emit(const int* __restrict__ start,
                                              const float* __restrict__ a,
                                              const float* __restrict__ bfreq) {
    __shared__ float sp[CHUNK][MTR];
    __shared__ int ss[CHUNK];
    const int tid = threadIdx.x;
    const int ck = blockIdx.x;
    const int t0 = ck * CHUNK;

    for (int idx = tid; idx < CHUNK * MTR; idx += 256)
        sp[idx >> 6][idx & 63] = g_pre[(size_t)(t0 + (idx >> 6)) * MTR + (idx & 63)];
    if (tid < CHUNK) ss[tid] = (start[t0 + tid] != 0);
    __syncthreads();

    const int m = tid >> 2;
    const int cg = tid & 3;
    const float gmag = expf(-fabsf(a[m]));
    float gre[4], gim[4], Sre[4], Sim[4];
#pragma unroll
    for (int q = 0; q < 4; q++) {
        int c = cg * 4 + q;
        float sv, cv; sincosf(bfreq[c], &sv, &cv);
        gre[q] = gmag * cv; gim[q] = gmag * sv;
        int ch = m * CCT + c;
        Sre[q] = g_cRe[(size_t)ck * NCH + ch];
        Sim[q] = g_cIm[(size_t)ck * NCH + ch];
    }
    for (int t = 0; t < CHUNK; t++) {
        float p = sp[t][m];
        float keep = ss[t] ? 0.f : 1.f;
#pragma unroll
        for (int q = 0; q < 4; q++) {
            float r  = keep * (gre[q] * Sre[q] - gim[q] * Sim[q]) + p;
            float im = keep * (gre[q] * Sim[q] + gim[q] * Sre[q]);
            Sre[q] = r; Sim[q] = im;
        }
        size_t base = (size_t)(t0 + t) * DMIX + (size_t)m * 32 + cg * 4;
        *(uint2*)(g_zin16 + base) = make_uint2(
            pack2h(__float2half_rn(Sre[0]), __float2half_rn(Sre[1])),
            pack2h(__float2half_rn(Sre[2]), __float2half_rn(Sre[3])));
        *(uint2*)(g_zin16 + base + 16) = make_uint2(
            pack2h(__float2half_rn(Sim[0]), __float2half_rn(Sim[1])),
            pack2h(__float2half_rn(Sim[2]), __float2half_rn(Sim[3])));
    }
}

// ---------------------------------------------------------------------------
// K3: out = z_in @ Wmix^T + x @ Wskip^T + biases (single-pass fp16 mma.sync).
// CTA 256x128, 8 warps (4m x 2n), warp tile 64x64.  XOR-swizzled 64B rows.
// 2-stage cp.async double buffer, CP_WAIT(0).
// ---------------------------------------------------------------------------
#define BM       256
#define BN       128
#define OFF_A    0
#define OFF_B    16384                    // A tile: 256x32 fp16 = 16KB
#define STG_SZ   24576                    // + B tile: 128x32 fp16 = 8KB
#define SM_TOTAL (1024 + 2 * STG_SZ)      // 50176
#define KTILES   (KTOT / 32)              // 96
#define MIXTILES (DMIX / 32)              // 64

__device__ __forceinline__ uint32_t swz(uint32_t row, uint32_t chunk) {
    return row * 64u + ((chunk ^ ((row >> 1) & 3u)) << 4);
}

__global__ __launch_bounds__(256, 1) void k_out_mma(const float* __restrict__ bmix,
                                                    const float* __restrict__ bskip,
                                                    float* __restrict__ out) {
    extern __shared__ char smem[];
    float* bias_s = (float*)smem;
    const uint32_t sb = smem_u32(smem);
    const int tid = threadIdx.x;
    const int lane = tid & 31, wid = tid >> 5;
    const int warp_m = wid & 3, warp_n = wid >> 2;     // 4x2 warps
    const int row0 = blockIdx.y * BM;
    const int col0 = blockIdx.x * BN;

    if (tid < BN) bias_s[tid] = bmix[col0 + tid] + bskip[col0 + tid];

    float acc[4][8][4];
#pragma unroll
    for (int i = 0; i < 4; i++)
#pragma unroll
        for (int j = 0; j < 8; j++)
#pragma unroll
            for (int q = 0; q < 4; q++) acc[i][j][q] = 0.f;

    // cp.async geometry: A = 1024 16B-chunks (256 rows x 4), B = 512 (128 x 4)
    const int c16a = tid & 3;
    const int rwA[4] = { tid >> 2, (tid + 256) >> 2, (tid + 512) >> 2, (tid + 768) >> 2 };
    const int rwB[2] = { tid >> 2, (tid + 256) >> 2 };
    uint32_t soffA[4], soffB[2];
#pragma unroll
    for (int r = 0; r < 4; r++) soffA[r] = swz((uint32_t)rwA[r], (uint32_t)c16a);
#pragma unroll
    for (int r = 0; r < 2; r++) soffB[r] = swz((uint32_t)rwB[r], (uint32_t)c16a);

    auto issue_cp = [&](int kt, uint32_t stg) {
        const bool mix = kt < MIXTILES;
        const __half* aP = mix ? g_zin16 : g_x16;
        const __half* bP = mix ? g_wm16 : g_ws16;
        const int ldx = mix ? DMIX : DIN;
        const int kk0 = (mix ? kt * 32 : (kt - MIXTILES) * 32) + c16a * 8;
#pragma unroll
        for (int r = 0; r < 4; r++)
            cp16(stg + OFF_A + soffA[r], aP + (size_t)(row0 + rwA[r]) * ldx + kk0);
#pragma unroll
        for (int r = 0; r < 2; r++)
            cp16(stg + OFF_B + soffB[r], bP + (size_t)(col0 + rwB[r]) * ldx + kk0);
        CP_COMMIT();
    };

    issue_cp(0, sb + 1024);

    // ldmatrix lane geometry (swizzle key invariant under row += 16)
    const uint32_t aRow = (uint32_t)(warp_m * 64 + (lane & 15));
    const uint32_t aHi  = (lane >> 4) & 1;
    const uint32_t keyA = (aRow >> 1) & 3;
    const uint32_t bRow = (uint32_t)(warp_n * 64 + (lane & 7) + (((lane >> 4) & 1) << 3));
    const uint32_t bHi  = (lane >> 3) & 1;
    const uint32_t keyB = (bRow >> 1) & 3;

    for (int kt = 0; kt < KTILES; kt++) {
        const uint32_t stg = sb + 1024 + (uint32_t)(kt & 1) * STG_SZ;
        CP_WAIT(0);
        __syncthreads();
        if (kt + 1 < KTILES)
            issue_cp(kt + 1, sb + 1024 + (uint32_t)((kt + 1) & 1) * STG_SZ);

#pragma unroll
        for (int s = 0; s < 2; s++) {
            const uint32_t cA = ((2u * s + aHi) ^ keyA) << 4;
            const uint32_t cB = ((2u * s + bHi) ^ keyB) << 4;
            const uint32_t aAddr = stg + OFF_A + aRow * 64 + cA;
            const uint32_t bAddr = stg + OFF_B + bRow * 64 + cB;
            uint32_t bh[16], afr[16];
#pragma unroll
            for (int jj = 0; jj < 4; jj++)
                ldsm4(bh + jj * 4, bAddr + (uint32_t)jj * 1024);
#pragma unroll
            for (int i = 0; i < 4; i++)
                ldsm4(afr + i * 4, aAddr + (uint32_t)i * 1024);
#pragma unroll
            for (int i = 0; i < 4; i++)
#pragma unroll
                for (int j = 0; j < 8; j++)
                    mma_f16(acc[i][j], afr + i * 4, bh + j * 2);
        }
    }

    const int r_base = row0 + warp_m * 64 + (lane >> 2);
    const int c_base = warp_n * 64 + (lane & 3) * 2;
#pragma unroll
    for (int i = 0; i < 4; i++) {
#pragma unroll
        for (int j = 0; j < 8; j++) {
            int r = r_base + i * 16;
            int c = c_base + j * 8;
            float b0 = bias_s[c], b1 = bias_s[c + 1];
            float2 v0 = make_float2(acc[i][j][0] + b0, acc[i][j][1] + b1);
            float2 v1 = make_float2(acc[i][j][2] + b0, acc[i][j][3] + b1);
            *(float2*)(out + (size_t)r * DOUT + col0 + c) = v0;
            *(float2*)(out + (size_t)(r + 8) * DOUT + col0 + c) = v1;
        }
    }
}

// ---------------------------------------------------------------------------
// Launch
// ---------------------------------------------------------------------------
extern "C" void kernel_launch(void* const* d_in, const int* in_sizes, int n_in,
                              void* d_out, int out_size) {
    const float* x     = (const float*)d_in[0];
    const float* s_re  = (const float*)d_in[1];
    const float* s_im  = (const float*)d_in[2];
    const int*   start = (const int*)d_in[3];
    const float* Wpre  = (const float*)d_in[5];
    const float* bpre  = (const float*)d_in[6];
    const float* Wskip = (const float*)d_in[7];
    const float* bskip = (const float*)d_in[8];
    const float* Wmix  = (const float*)d_in[9];
    const float* bmix  = (const float*)d_in[10];
    const float* a     = (const float*)d_in[11];
    const float* bf    = (const float*)d_in[12];
    float* out = (float*)d_out;
    float* stateOut = out + (size_t)TT * DOUT;

    cudaFuncSetAttribute(k_out_mma, cudaFuncAttributeMaxDynamicSharedMemorySize, SM_TOTAL);

    k_split<<<(N4_ALL + 255) / 256, 256>>>(x, Wmix, Wskip);
    k_pre<<<TT / 64, 256>>>(x, Wpre, bpre);
    k_chunk<<<NCHUNK, 256>>>(start, a, bf);
    k_chain<<<NCH / 32, 32>>>(s_re, s_im, a, bf, stateOut);
    k_emit<<<NCHUNK, 256>>>(start, a, bf);
    dim3 g3(DOUT / BN, TT / BM);
    k_out_mma<<<g3, 256, SM_TOTAL>>>(bmix, bskip, out);
}

// round 16
// speedup vs baseline: 1.2136x; 1.2136x over previous
#include <cuda_runtime.h>
#include <cuda_fp16.h>
#include <math.h>
#include <stdint.h>

#define TT      8192
#define DIN     1024
#define DOUT    1024
#define MTR     64
#define CCT     16
#define NCH     1024
#define CHUNK   32
#define NCHUNK  256           // TT/CHUNK
#define DMIX    2048
#define KTOT    (DMIX + DIN)  // 3072

// Scratch
__device__ float g_pre[TT * MTR];
__device__ float g_Bre[NCHUNK * NCH];
__device__ float g_Bim[NCHUNK * NCH];
__device__ float g_cRe[NCHUNK * NCH];
__device__ float g_cIm[NCHUNK * NCH];
__device__ int   g_any[NCHUNK];
// single fp16 planes for the big GEMM
__device__ __half g_zin16[TT * DMIX];
__device__ __half g_x16[TT * DIN];
__device__ __half g_wm16[DOUT * DMIX];
__device__ __half g_ws16[DOUT * DIN];

// ---------------------------------------------------------------------------
// helpers
// ---------------------------------------------------------------------------
__device__ __forceinline__ uint32_t smem_u32(const void* p) {
    uint32_t a;
    asm("{ .reg .u64 t; cvta.to.shared.u64 t, %1; cvt.u32.u64 %0, t; }" : "=r"(a) : "l"(p));
    return a;
}
__device__ __forceinline__ void ldsm4(uint32_t* r, uint32_t addr) {
    asm volatile("ldmatrix.sync.aligned.m8n8.x4.shared.b16 {%0,%1,%2,%3}, [%4];"
                 : "=r"(r[0]), "=r"(r[1]), "=r"(r[2]), "=r"(r[3]) : "r"(addr));
}
__device__ __forceinline__ void mma_f16(float* d, const uint32_t* a, const uint32_t* b) {
    asm volatile("mma.sync.aligned.m16n8k16.row.col.f32.f16.f16.f32 "
                 "{%0,%1,%2,%3}, {%4,%5,%6,%7}, {%8,%9}, {%0,%1,%2,%3};"
                 : "+f"(d[0]), "+f"(d[1]), "+f"(d[2]), "+f"(d[3])
                 : "r"(a[0]), "r"(a[1]), "r"(a[2]), "r"(a[3]), "r"(b[0]), "r"(b[1]));
}
__device__ __forceinline__ void cp16(uint32_t dst, const void* src) {
    asm volatile("cp.async.cg.shared.global [%0], [%1], 16;"
                 :: "r"(dst), "l"(src) : "memory");
}
#define CP_COMMIT() asm volatile("cp.async.commit_group;" ::: "memory")
#define CP_WAIT(n)  asm volatile("cp.async.wait_group %0;" :: "n"(n) : "memory")

__device__ __forceinline__ uint32_t pack2h(__half a, __half b) {
    return (uint32_t)__half_as_ushort(a) | ((uint32_t)__half_as_ushort(b) << 16);
}

// ---------------------------------------------------------------------------
// K0: x, Wmix, Wskip -> single fp16 planes
// ---------------------------------------------------------------------------
#define N4_X   (TT * DIN / 4)
#define N4_WM  (DOUT * DMIX / 4)
#define N4_WS  (DOUT * DIN / 4)
#define N4_ALL (N4_X + N4_WM + N4_WS)

__global__ __launch_bounds__(256) void k_split(const float* __restrict__ x,
                                               const float* __restrict__ Wmix,
                                               const float* __restrict__ Wskip) {
    int i = blockIdx.x * blockDim.x + threadIdx.x;
    if (i >= N4_ALL) return;
    const float* src; __half* dst; int j;
    if (i < N4_X)              { src = x;     dst = g_x16;  j = i; }
    else if (i < N4_X + N4_WM) { src = Wmix;  dst = g_wm16; j = i - N4_X; }
    else                       { src = Wskip; dst = g_ws16; j = i - N4_X - N4_WM; }
    float4 v = ((const float4*)src)[j];
    ((uint2*)dst)[j] = make_uint2(
        pack2h(__float2half_rn(v.x), __float2half_rn(v.y)),
        pack2h(__float2half_rn(v.z), __float2half_rn(v.w)));
}

// ---------------------------------------------------------------------------
// K1: pre = rownorm(x @ W_pre^T + b_pre)
// ---------------------------------------------------------------------------
__global__ __launch_bounds__(256) void k_pre(const float* __restrict__ x,
                                             const float* __restrict__ Wp,
                                             const float* __restrict__ bp) {
    __shared__ float xs[32][65];
    __shared__ float ws[32][65];
    __shared__ float nrm[64];
    const int tid = threadIdx.x;
    const int ty = tid >> 4, tx = tid & 15;
    const int row0 = blockIdx.x * 64;

    float acc[4][4];
#pragma unroll
    for (int i = 0; i < 4; i++)
#pragma unroll
        for (int j = 0; j < 4; j++) acc[i][j] = 0.f;

    for (int k0 = 0; k0 < DIN; k0 += 32) {
#pragma unroll
        for (int r = 0; r < 8; r++) {
            int idx = tid + r * 256;
            int m = idx >> 5, k = idx & 31;
            xs[k][m] = x[(size_t)(row0 + m) * DIN + k0 + k];
            ws[k][m] = Wp[(size_t)m * DIN + k0 + k];
        }
        __syncthreads();
#pragma unroll
        for (int kk = 0; kk < 32; kk++) {
            float av[4], bv[4];
#pragma unroll
            for (int i = 0; i < 4; i++) av[i] = xs[kk][ty * 4 + i];
#pragma unroll
            for (int j = 0; j < 4; j++) bv[j] = ws[kk][tx * 4 + j];
#pragma unroll
            for (int i = 0; i < 4; i++)
#pragma unroll
                for (int j = 0; j < 4; j++) acc[i][j] += av[i] * bv[j];
        }
        __syncthreads();
    }
#pragma unroll
    for (int j = 0; j < 4; j++) {
        float b = bp[tx * 4 + j];
#pragma unroll
        for (int i = 0; i < 4; i++) acc[i][j] += b;
    }
    if (tid < 64) nrm[tid] = 0.f;
    __syncthreads();
#pragma unroll
    for (int i = 0; i < 4; i++) {
        float s = 0.f;
#pragma unroll
        for (int j = 0; j < 4; j++) s += acc[i][j] * acc[i][j];
        atomicAdd(&nrm[ty * 4 + i], s);
    }
    __syncthreads();
#pragma unroll
    for (int i = 0; i < 4; i++) {
        float inv = 1.0f / (1e-6f + sqrtf(nrm[ty * 4 + i]));
#pragma unroll
        for (int j = 0; j < 4; j++)
            g_pre[(size_t)(row0 + ty * 4 + i) * MTR + tx * 4 + j] = acc[i][j] * inv;
    }
}

// ---------------------------------------------------------------------------
// K2a: per-chunk local scan from S=0 -> transfer (B, anyStart).  CHUNK=32.
// ---------------------------------------------------------------------------
__global__ __launch_bounds__(256) void k_chunk(const int* __restrict__ start,
                                               const float* __restrict__ a,
                                               const float* __restrict__ bfreq) {
    __shared__ float sp[CHUNK][MTR];
    __shared__ int ss[CHUNK];
    __shared__ int sAny;
    const int tid = threadIdx.x;
    const int ck = blockIdx.x;
    const int t0 = ck * CHUNK;

    for (int idx = tid; idx < CHUNK * MTR; idx += 256)
        sp[idx >> 6][idx & 63] = g_pre[(size_t)(t0 + (idx >> 6)) * MTR + (idx & 63)];
    if (tid < CHUNK) ss[tid] = (start[t0 + tid] != 0);
    if (tid == 0) sAny = 0;
    __syncthreads();
    if (tid < CHUNK && ss[tid]) atomicOr(&sAny, 1);

    const int m = tid >> 2;
    const float gmag = expf(-fabsf(a[m]));
    float gre[4], gim[4], Sre[4], Sim[4];
#pragma unroll
    for (int q = 0; q < 4; q++) {
        int c = ((tid & 3) << 2) + q;
        float sv, cv; sincosf(bfreq[c], &sv, &cv);
        gre[q] = gmag * cv; gim[q] = gmag * sv;
        Sre[q] = 0.f; Sim[q] = 0.f;
    }
    for (int t = 0; t < CHUNK; t++) {
        float p = sp[t][m];
        float keep = ss[t] ? 0.f : 1.f;
#pragma unroll
        for (int q = 0; q < 4; q++) {
            float r  = keep * (gre[q] * Sre[q] - gim[q] * Sim[q]) + p;
            float im = keep * (gre[q] * Sim[q] + gim[q] * Sre[q]);
            Sre[q] = r; Sim[q] = im;
        }
    }
#pragma unroll
    for (int q = 0; q < 4; q++) {
        int ch = tid * 4 + q;
        g_Bre[(size_t)ck * NCH + ch] = Sre[q];
        g_Bim[(size_t)ck * NCH + ch] = Sim[q];
    }
    __syncthreads();
    if (tid == 0) g_any[ck] = sAny;
}

// ---------------------------------------------------------------------------
// K2b: sequential chain, parallel over channels: 32 blocks x 32 channels.
// ---------------------------------------------------------------------------
#define CB 16
__global__ __launch_bounds__(32) void k_chain(const float* __restrict__ s_re0,
                                              const float* __restrict__ s_im0,
                                              const float* __restrict__ a,
                                              const float* __restrict__ bfreq,
                                              float* stateOut) {
    __shared__ float keep_s[NCHUNK];
    const int ch = blockIdx.x * 32 + threadIdx.x;
    const int m = ch >> 4, c = ch & 15;
    for (int idx = threadIdx.x; idx < NCHUNK; idx += 32)
        keep_s[idx] = g_any[idx] ? 0.f : 1.f;
    __syncthreads();

    const float Amag = expf(-(float)CHUNK * fabsf(a[m]));
    float sv, cv; sincosf((float)CHUNK * bfreq[c], &sv, &cv);
    const float Are = Amag * cv, Aim = Amag * sv;
    float Sre = s_re0[ch], Sim = s_im0[ch];

    for (int kb = 0; kb < NCHUNK; kb += CB) {
        float br[CB], bi[CB];
#pragma unroll
        for (int q = 0; q < CB; q++) {
            br[q] = g_Bre[(size_t)(kb + q) * NCH + ch];
            bi[q] = g_Bim[(size_t)(kb + q) * NCH + ch];
        }
#pragma unroll
        for (int q = 0; q < CB; q++) {
            g_cRe[(size_t)(kb + q) * NCH + ch] = Sre;
            g_cIm[(size_t)(kb + q) * NCH + ch] = Sim;
            float keep = keep_s[kb + q];
            float r  = keep * (Are * Sre - Aim * Sim) + br[q];
            float im = keep * (Are * Sim + Aim * Sre) + bi[q];
            Sre = r; Sim = im;
        }
    }
    stateOut[ch]       = Sre;   // planar: re then im
    stateOut[NCH + ch] = Sim;
}

// ---------------------------------------------------------------------------
// K2c: re-scan with true carry, emit zin as a single fp16 plane.  CHUNK=32.
// ---------------------------------------------------------------------------
__global__ __launch_bounds__(256) void k_emit(const int* __restrict__ start,
                                              const float* __restrict__ a,
                                              const float* __restrict__ bfreq) {
    __shared__ float sp[CHUNK][MTR];
    __shared__ int ss[CHUNK];
    const int tid = threadIdx.x;
    const int ck = blockIdx.x;
    const int t0 = ck * CHUNK;

    for (int idx = tid; idx < CHUNK * MTR; idx += 256)
        sp[idx >> 6][idx & 63] = g_pre[(size_t)(t0 + (idx >> 6)) * MTR + (idx & 63)];
    if (tid < CHUNK) ss[tid] = (start[t0 + tid] != 0);
    __syncthreads();

    const int m = tid >> 2;
    const int cg = tid & 3;
    const float gmag = expf(-fabsf(a[m]));
    float gre[4], gim[4], Sre[4], Sim[4];
#pragma unroll
    for (int q = 0; q < 4; q++) {
        int c = cg * 4 + q;
        float sv, cv; sincosf(bfreq[c], &sv, &cv);
        gre[q] = gmag * cv; gim[q] = gmag * sv;
        int ch = m * CCT + c;
        Sre[q] = g_cRe[(size_t)ck * NCH + ch];
        Sim[q] = g_cIm[(size_t)ck * NCH + ch];
    }
    for (int t = 0; t < CHUNK; t++) {
        float p = sp[t][m];
        float keep = ss[t] ? 0.f : 1.f;
#pragma unroll
        for (int q = 0; q < 4; q++) {
            float r  = keep * (gre[q] * Sre[q] - gim[q] * Sim[q]) + p;
            float im = keep * (gre[q] * Sim[q] + gim[q] * Sre[q]);
            Sre[q] = r; Sim[q] = im;
        }
        size_t base = (size_t)(t0 + t) * DMIX + (size_t)m * 32 + cg * 4;
        *(uint2*)(g_zin16 + base) = make_uint2(
            pack2h(__float2half_rn(Sre[0]), __float2half_rn(Sre[1])),
            pack2h(__float2half_rn(Sre[2]), __float2half_rn(Sre[3])));
        *(uint2*)(g_zin16 + base + 16) = make_uint2(
            pack2h(__float2half_rn(Sim[0]), __float2half_rn(Sim[1])),
            pack2h(__float2half_rn(Sim[2]), __float2half_rn(Sim[3])));
    }
}

// ---------------------------------------------------------------------------
// K3: out = z_in @ Wmix^T + x @ Wskip^T + biases (single-pass fp16 mma.sync).
// CTA 128x128, 4 warps (2x2), warp tile 64x64, 2 CTAs/SM.  BK=64:
// rows are 128B (8 x 16B chunks), swizzle chunk ^= (row & 7) -> conflict-free
// cp.async stores AND ldmatrix; key invariant under row += 16.
// 2-stage cp.async double buffer, CP_WAIT(0).
// ---------------------------------------------------------------------------
#define BK       64
#define OFF_A    0
#define OFF_B    16384                    // A tile: 128x64 fp16 = 16KB
#define STG_SZ   32768                    // + B tile: 128x64 fp16 = 16KB
#define SM_TOTAL (1024 + 2 * STG_SZ)      // 66560
#define KTILES   (KTOT / BK)              // 48
#define MIXTILES (DMIX / BK)              // 32

__device__ __forceinline__ uint32_t swz8(uint32_t row, uint32_t chunk) {
    return row * 128u + ((chunk ^ (row & 7u)) << 4);
}

__global__ __launch_bounds__(128, 2) void k_out_mma(const float* __restrict__ bmix,
                                                    const float* __restrict__ bskip,
                                                    float* __restrict__ out) {
    extern __shared__ char smem[];
    float* bias_s = (float*)smem;
    const uint32_t sb = smem_u32(smem);
    const int tid = threadIdx.x;
    const int lane = tid & 31, wid = tid >> 5;
    const int warp_m = wid & 1, warp_n = wid >> 1;     // 2x2 warps
    const int row0 = blockIdx.y * 128;
    const int col0 = blockIdx.x * 128;

    bias_s[tid] = bmix[col0 + tid] + bskip[col0 + tid];

    float acc[4][8][4];
#pragma unroll
    for (int i = 0; i < 4; i++)
#pragma unroll
        for (int j = 0; j < 8; j++)
#pragma unroll
            for (int q = 0; q < 4; q++) acc[i][j][q] = 0.f;

    // cp.async geometry: 1024 16B-chunks per array (128 rows x 8); 8 per thread
    const int c16a = tid & 7;
    const int rbase = tid >> 3;            // 0..15; +16 per pass
    uint32_t soffv[8];
#pragma unroll
    for (int r = 0; r < 8; r++)
        soffv[r] = swz8((uint32_t)(rbase + r * 16), (uint32_t)c16a);

    auto issue_cp = [&](int kt, uint32_t stg) {
        const bool mix = kt < MIXTILES;
        const __half* aP = mix ? g_zin16 : g_x16;
        const __half* bP = mix ? g_wm16 : g_ws16;
        const int ldx = mix ? DMIX : DIN;
        const int kk0 = (mix ? kt * BK : (kt - MIXTILES) * BK) + c16a * 8;
#pragma unroll
        for (int r = 0; r < 8; r++) {
            int rw = rbase + r * 16;
            cp16(stg + OFF_A + soffv[r], aP + (size_t)(row0 + rw) * ldx + kk0);
            cp16(stg + OFF_B + soffv[r], bP + (size_t)(col0 + rw) * ldx + kk0);
        }
        CP_COMMIT();
    };

    issue_cp(0, sb + 1024);

    // ldmatrix lane geometry (swizzle key invariant under row += 16)
    const uint32_t aRow = (uint32_t)(warp_m * 64 + (lane & 15));
    const uint32_t aHi  = (lane >> 4) & 1;
    const uint32_t keyA = aRow & 7;
    const uint32_t bRow = (uint32_t)(warp_n * 64 + (lane & 7) + (((lane >> 4) & 1) << 3));
    const uint32_t bHi  = (lane >> 3) & 1;
    const uint32_t keyB = bRow & 7;

    for (int kt = 0; kt < KTILES; kt++) {
        const uint32_t stg = sb + 1024 + (uint32_t)(kt & 1) * STG_SZ;
        CP_WAIT(0);
        __syncthreads();
        if (kt + 1 < KTILES)
            issue_cp(kt + 1, sb + 1024 + (uint32_t)((kt + 1) & 1) * STG_SZ);

#pragma unroll
        for (int s = 0; s < 4; s++) {
            const uint32_t cA = ((2u * s + aHi) ^ keyA) << 4;
            const uint32_t cB = ((2u * s + bHi) ^ keyB) << 4;
            const uint32_t aAddr = stg + OFF_A + aRow * 128 + cA;
            const uint32_t bAddr = stg + OFF_B + bRow * 128 + cB;
            uint32_t bh[16], afr[16];
#pragma unroll
            for (int jj = 0; jj < 4; jj++)
                ldsm4(bh + jj * 4, bAddr + (uint32_t)jj * 2048);
#pragma unroll
            for (int i = 0; i < 4; i++)
                ldsm4(afr + i * 4, aAddr + (uint32_t)i * 2048);
#pragma unroll
            for (int i = 0; i < 4; i++)
#pragma unroll
                for (int j = 0; j < 8; j++)
                    mma_f16(acc[i][j], afr + i * 4, bh + j * 2);
        }
    }

    const int r_base = row0 + warp_m * 64 + (lane >> 2);
    const int c_base = warp_n * 64 + (lane & 3) * 2;
#pragma unroll
    for (int i = 0; i < 4; i++) {
#pragma unroll
        for (int j = 0; j < 8; j++) {
            int r = r_base + i * 16;
            int c = c_base + j * 8;
            float b0 = bias_s[c], b1 = bias_s[c + 1];
            float2 v0 = make_float2(acc[i][j][0] + b0, acc[i][j][1] + b1);
            float2 v1 = make_float2(acc[i][j][2] + b0, acc[i][j][3] + b1);
            *(float2*)(out + (size_t)r * DOUT + col0 + c) = v0;
            *(float2*)(out + (size_t)(r + 8) * DOUT + col0 + c) = v1;
        }
    }
}

// ---------------------------------------------------------------------------
// Launch
// ---------------------------------------------------------------------------
extern "C" void kernel_launch(void* const* d_in, const int* in_sizes, int n_in,
                              void* d_out, int out_size) {
    const float* x     = (const float*)d_in[0];
    const float* s_re  = (const float*)d_in[1];
    const float* s_im  = (const float*)d_in[2];
    const int*   start = (const int*)d_in[3];
    const float* Wpre  = (const float*)d_in[5];
    const float* bpre  = (const float*)d_in[6];
    const float* Wskip = (const float*)d_in[7];
    const float* bskip = (const float*)d_in[8];
    const float* Wmix  = (const float*)d_in[9];
    const float* bmix  = (const float*)d_in[10];
    const float* a     = (const float*)d_in[11];
    const float* bf    = (const float*)d_in[12];
    float* out = (float*)d_out;
    float* stateOut = out + (size_t)TT * DOUT;

    cudaFuncSetAttribute(k_out_mma, cudaFuncAttributeMaxDynamicSharedMemorySize, SM_TOTAL);

    k_split<<<(N4_ALL + 255) / 256, 256>>>(x, Wmix, Wskip);
    k_pre<<<TT / 64, 256>>>(x, Wpre, bpre);
    k_chunk<<<NCHUNK, 256>>>(start, a, bf);
    k_chain<<<NCH / 32, 32>>>(s_re, s_im, a, bf, stateOut);
    k_emit<<<NCHUNK, 256>>>(start, a, bf);
    dim3 g3(DOUT / 128, TT / 128);
    k_out_mma<<<g3, 128, SM_TOTAL>>>(bmix, bskip, out);
}